// round 13
// baseline (speedup 1.0000x reference)
#include <cuda_runtime.h>
#include <cuda_fp16.h>
#include <cstdint>

#define Bsz 8
#define Cch 64
#define Hh  128
#define Wwi 128
#define Och 64
#define HW  (Hh*Wwi)

#define THREADS 256
#define NTILES  (Bsz*Hh)        // 1024 blocks, 1 tile each
#define NSUPER  4
#define NPH     9
#define NSTEPS  (NSUPER*NPH)    // 36

// smem (uint32 units): two buffers of
//   x packed half2 pairs: [8 pairch][3*132], stride 408 (408%32==24: conflict-free)
//   gc packed half2 pairs: [8 pairch][128], stride 136 (136%32==8: conflict-free)
#define PSTR    408
#define GC_OFF  (8*PSTR)        // 3264
#define GCSTR   136
#define BUF_U   (GC_OFF + 8*GCSTR)   // 4352 u32 = 17408 B
#define SMEM_U  (2*BUF_U)            // 8704 u32 = 34816 B

#define XP_ELEMS 3168           // 8 * 3*132
#define XP_ITERS 13
#define GC_ITERS 4              // 8*128/256

// B fragments: [step=36][j=4][lane=32] x uint4, lane innermost (coalesced)
__device__ uint4 d_bfrag[NSTEPS*4*32];

// ---------------- helpers ----------------
__device__ __forceinline__ uint32_t packh2(float lo, float hi) {
    __half2 h = __floats2half2_rn(lo, hi);
    return *reinterpret_cast<uint32_t*>(&h);
}
__device__ __forceinline__ uint32_t hadd2(uint32_t a, uint32_t b) {
    uint32_t r; asm("add.f16x2 %0, %1, %2;" : "=r"(r) : "r"(a), "r"(b)); return r;
}
__device__ __forceinline__ uint32_t tanh_h2(uint32_t a) {
    uint32_t r; asm("tanh.approx.f16x2 %0, %1;" : "=r"(r) : "r"(a)); return r;
}
__device__ __forceinline__ uint32_t hfma2(uint32_t a, uint32_t b, uint32_t c) {
    uint32_t r; asm("fma.rn.f16x2 %0, %1, %2, %3;" : "=r"(r) : "r"(a), "r"(b), "r"(c)); return r;
}
__device__ __forceinline__ void hmma(float& c0, float& c1, float& c2, float& c3,
                                     uint32_t a0, uint32_t a1, uint32_t a2, uint32_t a3,
                                     uint32_t b0, uint32_t b1) {
    asm("mma.sync.aligned.m16n8k16.row.col.f32.f16.f16.f32 "
        "{%0,%1,%2,%3}, {%4,%5,%6,%7}, {%8,%9}, {%0,%1,%2,%3};"
        : "+f"(c0), "+f"(c1), "+f"(c2), "+f"(c3)
        : "r"(a0), "r"(a1), "r"(a2), "r"(a3), "r"(b0), "r"(b1));
}

// ---------------- B fragment prep: step (g,p), slot s -> w[o][g*16+s][p] ----
__global__ void prep_bfrag(const float* __restrict__ w) {
    int i = blockIdx.x * blockDim.x + threadIdx.x;   // [step][j][lane]
    if (i < NSTEPS*4*32) {
        int lane = i & 31;
        int j    = (i >> 5) & 3;
        int step = i >> 7;
        int g    = step / NPH;
        int p    = step - g*NPH;
        int kb   = (lane & 3) * 2;
        uint32_t v[4];
        #pragma unroll
        for (int t = 0; t < 2; ++t) {
            int nt = 2*j + t;
            int o  = nt*8 + (lane >> 2);
            float f[4];
            #pragma unroll
            for (int q = 0; q < 4; ++q) {
                int s = kb + (q >> 1)*8 + (q & 1);
                int c = g*16 + s;
                f[q] = w[(o*Cch + c)*9 + p];
            }
            v[2*t]   = packh2(f[0], f[1]);
            v[2*t+1] = packh2(f[2], f[3]);
        }
        uint4 r; r.x = v[0]; r.y = v[1]; r.z = v[2]; r.w = v[3];
        d_bfrag[i] = r;
    }
}

// ---------------- staging: LDG f32 pairs -> packed half2 regs ----------------
__device__ __forceinline__ void ldg_chunk(const float* __restrict__ xB,
                                          const float* __restrict__ gcR,
                                          int cg, int h, int tid,
                                          uint32_t xr[XP_ITERS], uint32_t gr[GC_ITERS])
{
    const float* xc = xB + (size_t)cg*16*HW;
    #pragma unroll
    for (int it = 0; it < XP_ITERS; ++it) {
        int idx = tid + it*THREADS;
        uint32_t v = 0;
        if (idx < XP_ELEMS) {
            int pc  = idx / 396;
            int rem = idx - pc*396;
            int r4  = rem / 132;
            int col = rem - r4*132;
            int gh  = h - 1 + r4;
            int gw  = col - 1;
            if (((unsigned)gh < Hh) & ((unsigned)gw < Wwi)) {
                const float* s = xc + (size_t)(2*pc)*HW + gh*Wwi + gw;
                v = packh2(__ldg(s), __ldg(s + HW));
            }
        }
        xr[it] = v;
    }
    const float* gcc = gcR + (size_t)cg*16*HW;
    #pragma unroll
    for (int it = 0; it < GC_ITERS; ++it) {
        int idx = tid + it*THREADS;
        int pc  = idx >> 7;
        int col = idx & 127;
        const float* s = gcc + (size_t)(2*pc)*HW + col;
        gr[it] = packh2(__ldg(s), __ldg(s + HW));
    }
}
__device__ __forceinline__ void sts_chunk(uint32_t* __restrict__ bsu, int tid,
                                          const uint32_t xr[XP_ITERS],
                                          const uint32_t gr[GC_ITERS])
{
    #pragma unroll
    for (int it = 0; it < XP_ITERS; ++it) {
        int idx = tid + it*THREADS;
        if (idx < XP_ELEMS) {
            int pc  = idx / 396;
            int rem = idx - pc*396;
            int r4  = rem / 132;
            int col = rem - r4*132;
            bsu[pc*PSTR + r4*132 + col] = xr[it];
        }
    }
    #pragma unroll
    for (int it = 0; it < GC_ITERS; ++it) {
        int idx = tid + it*THREADS;
        int pc  = idx >> 7;
        int col = idx & 127;
        bsu[GC_OFF + pc*GCSTR + col] = gr[it];
    }
}

// ---------------- main kernel ----------------
extern __shared__ uint32_t smu[];

__global__ void __launch_bounds__(THREADS, 2)
paka_hmma(const float* __restrict__ x,
          const float* __restrict__ gc,
          const float* __restrict__ gsp,
          float* __restrict__ out)
{
    const int tid  = threadIdx.x;
    const int lane = tid & 31;
    const int wid  = tid >> 5;
    const int t    = blockIdx.x;
    const int b    = t >> 7;
    const int h    = t & 127;

    const float* xB  = x  + (size_t)b*Cch*HW;
    const float* gcR = gc + (size_t)b*Cch*HW + (size_t)h*Wwi;

    uint32_t xr[XP_ITERS], gr[GC_ITERS];
    ldg_chunk(xB, gcR, 0, h, tid, xr, gr);

    const int r0 = wid*16 + (lane >> 2);
    const int r1 = r0 + 8;
    const int qp = (lane & 3)*2;
    const int pcA = lane & 3;           // pair-channel index (qp/2)

    // gs broadcast half2 for all 9 phases x 2 rows
    const float* gsb = gsp + (size_t)b*9*HW + (size_t)h*Wwi;
    uint32_t gs2a[9], gs2b[9];
    #pragma unroll
    for (int p = 0; p < 9; ++p) {
        float v0 = __ldg(gsb + (size_t)p*HW + r0);
        float v1 = __ldg(gsb + (size_t)p*HW + r1);
        gs2a[p] = packh2(v0, v0);
        gs2b[p] = packh2(v1, v1);
    }

    float acc[32];
    #pragma unroll
    for (int i = 0; i < 32; ++i) acc[i] = 0.f;

    for (int g = 0; g < NSUPER; ++g) {
        uint32_t* bsu = smu + (g & 1)*BUF_U;
        sts_chunk(bsu, tid, xr, gr);
        __syncthreads();                 // chunk visible; prior reads of this buf done 2 iters ago
        if (g + 1 < NSUPER) ldg_chunk(xB, gcR, g + 1, h, tid, xr, gr);

        // base pointers: pair (qp,qp+1) and (qp+8,qp+9) at rows r0/r1
        const uint32_t* q0 = bsu + pcA*PSTR + r0;      // +imm; +1632 for pair+4
        const uint32_t* q1 = bsu + pcA*PSTR + r1;

        const uint32_t c2_0 = bsu[GC_OFF + pcA*GCSTR + r0];
        const uint32_t c2_1 = bsu[GC_OFF + pcA*GCSTR + r1];
        const uint32_t c2_2 = bsu[GC_OFF + (pcA + 4)*GCSTR + r0];
        const uint32_t c2_3 = bsu[GC_OFF + (pcA + 4)*GCSTR + r1];

        #pragma unroll
        for (int p = 0; p < NPH; ++p) {
            const int di  = p / 3;
            const int dj  = p - 3*di;
            const int imm = di*132 + dj;

            const uint4* bp = d_bfrag + (size_t)(g*NPH + p)*128 + lane;
            uint4 B0 = bp[0];
            uint4 B1 = bp[32];

            // pre-packed half2 channel pairs: 4 LDS.32, no packs
            const uint32_t xp0 = q0[imm];
            const uint32_t xp1 = q1[imm];
            const uint32_t xp2 = q0[4*PSTR + imm];
            const uint32_t xp3 = q1[4*PSTR + imm];

            const uint32_t t0 = tanh_h2(hadd2(c2_0, gs2a[p]));
            const uint32_t t1 = tanh_h2(hadd2(c2_1, gs2b[p]));
            const uint32_t t2 = tanh_h2(hadd2(c2_2, gs2a[p]));
            const uint32_t t3 = tanh_h2(hadd2(c2_3, gs2b[p]));

            const uint32_t a0 = hfma2(xp0, t0, xp0);
            const uint32_t a1 = hfma2(xp1, t1, xp1);
            const uint32_t a2 = hfma2(xp2, t2, xp2);
            const uint32_t a3 = hfma2(xp3, t3, xp3);

            hmma(acc[0],  acc[1],  acc[2],  acc[3],  a0,a1,a2,a3, B0.x, B0.y);
            hmma(acc[4],  acc[5],  acc[6],  acc[7],  a0,a1,a2,a3, B0.z, B0.w);
            hmma(acc[8],  acc[9],  acc[10], acc[11], a0,a1,a2,a3, B1.x, B1.y);
            hmma(acc[12], acc[13], acc[14], acc[15], a0,a1,a2,a3, B1.z, B1.w);

            uint4 B2 = bp[64];
            uint4 B3 = bp[96];
            hmma(acc[16], acc[17], acc[18], acc[19], a0,a1,a2,a3, B2.x, B2.y);
            hmma(acc[20], acc[21], acc[22], acc[23], a0,a1,a2,a3, B2.z, B2.w);
            hmma(acc[24], acc[25], acc[26], acc[27], a0,a1,a2,a3, B3.x, B3.y);
            hmma(acc[28], acc[29], acc[30], acc[31], a0,a1,a2,a3, B3.z, B3.w);
        }
        __syncthreads();   // all reads of bsu done before it is re-stored next round
    }

    // ---- epilogue ----
    float* ob = out + ((size_t)b*Och)*HW + (size_t)h*Wwi;
    #pragma unroll
    for (int nt = 0; nt < 8; ++nt) {
        const int o0 = nt*8 + qp;
        float* p = ob + (size_t)o0*HW;
        p[r0]      = acc[nt*4 + 0];
        p[HW + r0] = acc[nt*4 + 1];
        p[r1]      = acc[nt*4 + 2];
        p[HW + r1] = acc[nt*4 + 3];
    }
}

extern "C" void kernel_launch(void* const* d_in, const int* in_sizes, int n_in,
                              void* d_out, int out_size) {
    const float* x  = (const float*)d_in[0];
    const float* gc = (const float*)d_in[1];
    const float* gs = (const float*)d_in[2];
    const float* w  = (const float*)d_in[3];
    float* out = (float*)d_out;

    prep_bfrag<<<(NSTEPS*4*32 + 255)/256, 256>>>(w);

    const int smem_bytes = SMEM_U * 4;
    (void)cudaFuncSetAttribute(paka_hmma,
                               cudaFuncAttributeMaxDynamicSharedMemorySize,
                               smem_bytes);
    paka_hmma<<<NTILES, THREADS, smem_bytes>>>(x, gc, gs, out);
}

// round 14
// speedup vs baseline: 1.1645x; 1.1645x over previous
#include <cuda_runtime.h>
#include <cuda_fp16.h>
#include <cstdint>

#define Bsz 8
#define Cch 64
#define Hh  128
#define Wwi 128
#define Och 64
#define HW  (Hh*Wwi)

#define THREADS 256
#define NTILES  (Bsz*Hh)        // 1024 blocks, 1 tile each
#define NSUPER  4               // super-groups of 16 channels
#define NPH     9               // phases per super-group
#define NSTEPS  (NSUPER*NPH)    // 36

// smem (floats): two chunk buffers [x: 16ch x (3*132), stride 404 | gc: 16 x 132]
// + gs half2 packs [9][128] (u32, broadcast per pixel)
#define XSTR    404
#define XGC_OFF (16*XSTR)              // 6464
#define GCSTR   132
#define BUF_FL  (XGC_OFF + 16*GCSTR)   // 8576
#define GS_OFF  (2*BUF_FL)             // 17152
#define SMEM_FL (GS_OFF + 9*128)       // 18304 fl/u32 = 73216 B

#define X_ELEMS (16*3*132)             // 6336

// B fragments: [step=36][j=4][lane=32] x uint4, lane innermost (coalesced)
__device__ uint4 d_bfrag[NSTEPS*4*32];

// ---------------- helpers ----------------
__device__ __forceinline__ uint32_t smem_u32(const void* p) {
    uint32_t a;
    asm("{ .reg .u64 t; cvta.to.shared.u64 t, %1; cvt.u32.u64 %0, t; }"
        : "=r"(a) : "l"(p));
    return a;
}
__device__ __forceinline__ void cp4(uint32_t dst, const void* src, int nbytes) {
    asm volatile("cp.async.ca.shared.global [%0], [%1], 4, %2;"
                 :: "r"(dst), "l"(src), "r"(nbytes));
}
__device__ __forceinline__ void cp_commit() { asm volatile("cp.async.commit_group;"); }
__device__ __forceinline__ void cp_wait1()  { asm volatile("cp.async.wait_group 1;" ::: "memory"); }
__device__ __forceinline__ void cp_wait0()  { asm volatile("cp.async.wait_group 0;" ::: "memory"); }
__device__ __forceinline__ uint32_t packh2(float lo, float hi) {
    __half2 h = __floats2half2_rn(lo, hi);
    return *reinterpret_cast<uint32_t*>(&h);
}
__device__ __forceinline__ uint32_t hadd2(uint32_t a, uint32_t b) {
    uint32_t r; asm("add.f16x2 %0, %1, %2;" : "=r"(r) : "r"(a), "r"(b)); return r;
}
__device__ __forceinline__ uint32_t tanh_h2(uint32_t a) {
    uint32_t r; asm("tanh.approx.f16x2 %0, %1;" : "=r"(r) : "r"(a)); return r;
}
__device__ __forceinline__ uint32_t hfma2(uint32_t a, uint32_t b, uint32_t c) {
    uint32_t r; asm("fma.rn.f16x2 %0, %1, %2, %3;" : "=r"(r) : "r"(a), "r"(b), "r"(c)); return r;
}
__device__ __forceinline__ void hmma(float& c0, float& c1, float& c2, float& c3,
                                     uint32_t a0, uint32_t a1, uint32_t a2, uint32_t a3,
                                     uint32_t b0, uint32_t b1) {
    asm("mma.sync.aligned.m16n8k16.row.col.f32.f16.f16.f32 "
        "{%0,%1,%2,%3}, {%4,%5,%6,%7}, {%8,%9}, {%0,%1,%2,%3};"
        : "+f"(c0), "+f"(c1), "+f"(c2), "+f"(c3)
        : "r"(a0), "r"(a1), "r"(a2), "r"(a3), "r"(b0), "r"(b1));
}

// ---------------- B fragment prep: step (g,p), slot s -> w[o][g*16+s][p] ----
__global__ void prep_bfrag(const float* __restrict__ w) {
    int i = blockIdx.x * blockDim.x + threadIdx.x;   // [step][j][lane]
    if (i < NSTEPS*4*32) {
        int lane = i & 31;
        int j    = (i >> 5) & 3;
        int step = i >> 7;
        int g    = step / NPH;
        int p    = step - g*NPH;
        int kb   = (lane & 3) * 2;
        uint32_t v[4];
        #pragma unroll
        for (int t = 0; t < 2; ++t) {
            int nt = 2*j + t;
            int o  = nt*8 + (lane >> 2);
            float f[4];
            #pragma unroll
            for (int q = 0; q < 4; ++q) {
                int s = kb + (q >> 1)*8 + (q & 1);
                int c = g*16 + s;
                f[q] = w[(o*Cch + c)*9 + p];
            }
            v[2*t]   = packh2(f[0], f[1]);
            v[2*t+1] = packh2(f[2], f[3]);
        }
        uint4 r; r.x = v[0]; r.y = v[1]; r.z = v[2]; r.w = v[3];
        d_bfrag[i] = r;
    }
}

// ---------------- main kernel ----------------
extern __shared__ float sm[];

__global__ void __launch_bounds__(THREADS, 3)
paka_hmma(const float* __restrict__ x,
          const float* __restrict__ gc,
          const float* __restrict__ gsp,
          float* __restrict__ out)
{
    const int tid  = threadIdx.x;
    const int lane = tid & 31;
    const int wid  = tid >> 5;
    const int t    = blockIdx.x;
    const int b    = t >> 7;
    const int h    = t & 127;

    const uint32_t sbase = smem_u32(sm);

    // ---- stage gs half2 packs into smem (once per tile) ----
    {
        uint32_t* gsm = (uint32_t*)(sm + GS_OFF);
        const float* gsb = gsp + (size_t)b*9*HW + (size_t)h*Wwi;
        #pragma unroll
        for (int it = 0; it < 5; ++it) {
            int idx = tid + it*THREADS;
            if (idx < 9*128) {
                int p   = idx >> 7;
                int col = idx & 127;
                float v = __ldg(gsb + (size_t)p*HW + col);
                gsm[idx] = packh2(v, v);
            }
        }
    }

    // ---- staging ----
    const float* xB  = x  + (size_t)b*Cch*HW;
    const float* gcB = gc + (size_t)b*Cch*HW + (size_t)h*Wwi;
    auto stage_chunk = [&](int cg) {
        const uint32_t dst = sbase + (cg & 1)*BUF_FL*4;
        const float* xc = xB + (size_t)cg*16*HW;
        #pragma unroll
        for (int it = 0; it < 25; ++it) {
            int idx = tid + it*THREADS;
            if (idx < X_ELEMS) {
                int r   = (int)(((unsigned)idx * 31776u) >> 22);   // idx/132
                int col = idx - r*132;
                int cl  = (r*86) >> 8;                             // r/3
                int di  = r - 3*cl;
                int gh  = h - 1 + di;
                int gw  = col - 1;
                bool inb = ((unsigned)gh < Hh) & ((unsigned)gw < Wwi);
                const float* src = inb ? (xc + (size_t)cl*HW + gh*Wwi + gw) : xB;
                cp4(dst + (uint32_t)(cl*XSTR + di*132 + col)*4, src, inb ? 4 : 0);
            }
        }
        const float* gcc = gcB + (size_t)cg*16*HW;
        #pragma unroll
        for (int it = 0; it < 8; ++it) {
            int idx = tid + it*THREADS;
            int cl = idx >> 7, w = idx & 127;
            cp4(dst + (uint32_t)(XGC_OFF + cl*GCSTR + w)*4, gcc + (size_t)cl*HW + w, 4);
        }
    };
    stage_chunk(0);
    cp_commit();

    const int r0 = wid*16 + (lane >> 2);
    const int r1 = r0 + 8;
    const int qp = (lane & 3)*2;

    float acc[32];
    #pragma unroll
    for (int i = 0; i < 32; ++i) acc[i] = 0.f;

    const uint32_t* gsm = (const uint32_t*)(sm + GS_OFF);

    for (int g = 0; g < NSUPER; ++g) {
        if (g + 1 < NSUPER) { stage_chunk(g + 1); cp_commit(); cp_wait1(); }
        else                { cp_wait0(); }
        __syncthreads();

        const float* bs = sm + (g & 1)*BUF_FL;
        // per-thread channel base pointers (channels qp, qp+1, qp+8, qp+9)
        const float* p00 = bs + (qp    )*XSTR + r0;
        const float* p01 = bs + (qp    )*XSTR + r1;
        const float* p10 = bs + (qp + 1)*XSTR + r0;
        const float* p11 = bs + (qp + 1)*XSTR + r1;
        const float* p20 = bs + (qp + 8)*XSTR + r0;
        const float* p21 = bs + (qp + 8)*XSTR + r1;
        const float* p30 = bs + (qp + 9)*XSTR + r0;
        const float* p31 = bs + (qp + 9)*XSTR + r1;

        // gc channel-pairs packed to half2, hoisted per super-group
        const float* gp = bs + XGC_OFF;
        const uint32_t gc2_0 = packh2(gp[(qp    )*GCSTR + r0], gp[(qp + 1)*GCSTR + r0]);
        const uint32_t gc2_1 = packh2(gp[(qp    )*GCSTR + r1], gp[(qp + 1)*GCSTR + r1]);
        const uint32_t gc2_2 = packh2(gp[(qp + 8)*GCSTR + r0], gp[(qp + 9)*GCSTR + r0]);
        const uint32_t gc2_3 = packh2(gp[(qp + 8)*GCSTR + r1], gp[(qp + 9)*GCSTR + r1]);

        #pragma unroll
        for (int p = 0; p < NPH; ++p) {
            const int di  = p / 3;
            const int dj  = p - 3*di;
            const int imm = di*132 + dj;          // compile-time after unroll

            const uint4* bp = d_bfrag + (size_t)(g*NPH + p)*128 + lane;
            uint4 B0 = bp[0];
            uint4 B1 = bp[32];

            // gs broadcast packs from smem (conflict-free, broadcast in quads)
            const uint32_t gsa = gsm[p*128 + r0];
            const uint32_t gsb2 = gsm[p*128 + r1];

            // x channel-pairs packed to half2
            const uint32_t xp0 = packh2(p00[imm], p10[imm]);
            const uint32_t xp1 = packh2(p01[imm], p11[imm]);
            const uint32_t xp2 = packh2(p20[imm], p30[imm]);
            const uint32_t xp3 = packh2(p21[imm], p31[imm]);

            const uint32_t t0 = tanh_h2(hadd2(gc2_0, gsa));
            const uint32_t t1 = tanh_h2(hadd2(gc2_1, gsb2));
            const uint32_t t2 = tanh_h2(hadd2(gc2_2, gsa));
            const uint32_t t3 = tanh_h2(hadd2(gc2_3, gsb2));

            const uint32_t a0 = hfma2(xp0, t0, xp0);
            const uint32_t a1 = hfma2(xp1, t1, xp1);
            const uint32_t a2 = hfma2(xp2, t2, xp2);
            const uint32_t a3 = hfma2(xp3, t3, xp3);

            hmma(acc[0],  acc[1],  acc[2],  acc[3],  a0,a1,a2,a3, B0.x, B0.y);
            hmma(acc[4],  acc[5],  acc[6],  acc[7],  a0,a1,a2,a3, B0.z, B0.w);
            hmma(acc[8],  acc[9],  acc[10], acc[11], a0,a1,a2,a3, B1.x, B1.y);
            hmma(acc[12], acc[13], acc[14], acc[15], a0,a1,a2,a3, B1.z, B1.w);

            uint4 B2 = bp[64];
            uint4 B3 = bp[96];
            hmma(acc[16], acc[17], acc[18], acc[19], a0,a1,a2,a3, B2.x, B2.y);
            hmma(acc[20], acc[21], acc[22], acc[23], a0,a1,a2,a3, B2.z, B2.w);
            hmma(acc[24], acc[25], acc[26], acc[27], a0,a1,a2,a3, B3.x, B3.y);
            hmma(acc[28], acc[29], acc[30], acc[31], a0,a1,a2,a3, B3.z, B3.w);
        }
        __syncthreads();   // all done reading bs before restaging
    }

    // ---- epilogue: D fragments -> out[b][o][h][w] ----
    float* ob = out + ((size_t)b*Och)*HW + (size_t)h*Wwi;
    #pragma unroll
    for (int nt = 0; nt < 8; ++nt) {
        const int o0 = nt*8 + qp;
        float* p = ob + (size_t)o0*HW;
        p[r0]      = acc[nt*4 + 0];
        p[HW + r0] = acc[nt*4 + 1];
        p[r1]      = acc[nt*4 + 2];
        p[HW + r1] = acc[nt*4 + 3];
    }
}

extern "C" void kernel_launch(void* const* d_in, const int* in_sizes, int n_in,
                              void* d_out, int out_size) {
    const float* x  = (const float*)d_in[0];
    const float* gc = (const float*)d_in[1];
    const float* gs = (const float*)d_in[2];
    const float* w  = (const float*)d_in[3];
    float* out = (float*)d_out;

    prep_bfrag<<<(NSTEPS*4*32 + 255)/256, 256>>>(w);

    const int smem_bytes = SMEM_FL * 4;
    (void)cudaFuncSetAttribute(paka_hmma,
                               cudaFuncAttributeMaxDynamicSharedMemorySize,
                               smem_bytes);
    paka_hmma<<<NTILES, THREADS, smem_bytes>>>(x, gc, gs, out);
}

// round 15
// speedup vs baseline: 1.5468x; 1.3283x over previous
#include <cuda_runtime.h>
#include <cuda_fp16.h>
#include <cstdint>

#define Bsz 8
#define Cch 64
#define Hh  128
#define Wwi 128
#define Och 64
#define HW  (Hh*Wwi)

#define THREADS 256
#define NTILES  (Bsz*Hh)        // 1024 blocks, 1 tile each
#define NSUPER  4
#define NPH     9
#define NSTEPS  (NSUPER*NPH)    // 36

// smem (floats): two chunk buffers
//   x: 16ch x 3 halo rows, row pitch 136: [0..3]=left pad (col3 = gw=-1, zero),
//      [4..131] = gw 0..127, [132..135] = right pad (col132 = gw=128, zero)
//   channel stride XSTR=420 (≡4 mod 16 -> pair-groups hit banks 0/8/16/24; ≡0 mod 4 -> 16B-aligned rows)
//   gc: 16 x 132
#define ROWP    136
#define XSTR    420
#define XGC_OFF (16*XSTR)              // 6720
#define GCSTR   132
#define BUF_FL  (XGC_OFF + 16*GCSTR)   // 8832
#define SMEM_FL (2*BUF_FL)             // 17664 fl = 70656 B

// B fragments: [step=36][j=4][lane=32] x uint4, lane innermost (coalesced)
__device__ uint4 d_bfrag[NSTEPS*4*32];

// ---------------- helpers ----------------
__device__ __forceinline__ uint32_t smem_u32(const void* p) {
    uint32_t a;
    asm("{ .reg .u64 t; cvta.to.shared.u64 t, %1; cvt.u32.u64 %0, t; }"
        : "=r"(a) : "l"(p));
    return a;
}
__device__ __forceinline__ void cp16(uint32_t dst, const void* src, int nbytes) {
    asm volatile("cp.async.cg.shared.global [%0], [%1], 16, %2;"
                 :: "r"(dst), "l"(src), "r"(nbytes));
}
__device__ __forceinline__ void cp_commit() { asm volatile("cp.async.commit_group;"); }
__device__ __forceinline__ void cp_wait1()  { asm volatile("cp.async.wait_group 1;" ::: "memory"); }
__device__ __forceinline__ void cp_wait0()  { asm volatile("cp.async.wait_group 0;" ::: "memory"); }
__device__ __forceinline__ uint32_t packh2(float lo, float hi) {
    __half2 h = __floats2half2_rn(lo, hi);
    return *reinterpret_cast<uint32_t*>(&h);
}
__device__ __forceinline__ uint32_t hadd2(uint32_t a, uint32_t b) {
    uint32_t r; asm("add.f16x2 %0, %1, %2;" : "=r"(r) : "r"(a), "r"(b)); return r;
}
__device__ __forceinline__ uint32_t tanh_h2(uint32_t a) {
    uint32_t r; asm("tanh.approx.f16x2 %0, %1;" : "=r"(r) : "r"(a)); return r;
}
__device__ __forceinline__ uint32_t hfma2(uint32_t a, uint32_t b, uint32_t c) {
    uint32_t r; asm("fma.rn.f16x2 %0, %1, %2, %3;" : "=r"(r) : "r"(a), "r"(b), "r"(c)); return r;
}
__device__ __forceinline__ void hmma(float& c0, float& c1, float& c2, float& c3,
                                     uint32_t a0, uint32_t a1, uint32_t a2, uint32_t a3,
                                     uint32_t b0, uint32_t b1) {
    asm("mma.sync.aligned.m16n8k16.row.col.f32.f16.f16.f32 "
        "{%0,%1,%2,%3}, {%4,%5,%6,%7}, {%8,%9}, {%0,%1,%2,%3};"
        : "+f"(c0), "+f"(c1), "+f"(c2), "+f"(c3)
        : "r"(a0), "r"(a1), "r"(a2), "r"(a3), "r"(b0), "r"(b1));
}

// ---------------- B fragment prep: step (g,p), slot s -> w[o][g*16+s][p] ----
__global__ void prep_bfrag(const float* __restrict__ w) {
    int i = blockIdx.x * blockDim.x + threadIdx.x;   // [step][j][lane]
    if (i < NSTEPS*4*32) {
        int lane = i & 31;
        int j    = (i >> 5) & 3;
        int step = i >> 7;
        int g    = step / NPH;
        int p    = step - g*NPH;
        int kb   = (lane & 3) * 2;
        uint32_t v[4];
        #pragma unroll
        for (int t = 0; t < 2; ++t) {
            int nt = 2*j + t;
            int o  = nt*8 + (lane >> 2);
            float f[4];
            #pragma unroll
            for (int q = 0; q < 4; ++q) {
                int s = kb + (q >> 1)*8 + (q & 1);
                int c = g*16 + s;
                f[q] = w[(o*Cch + c)*9 + p];
            }
            v[2*t]   = packh2(f[0], f[1]);
            v[2*t+1] = packh2(f[2], f[3]);
        }
        uint4 r; r.x = v[0]; r.y = v[1]; r.z = v[2]; r.w = v[3];
        d_bfrag[i] = r;
    }
}

// ---------------- main kernel ----------------
extern __shared__ float sm[];

__global__ void __launch_bounds__(THREADS, 2)
paka_hmma(const float* __restrict__ x,
          const float* __restrict__ gc,
          const float* __restrict__ gsp,
          float* __restrict__ out)
{
    const int tid  = threadIdx.x;
    const int lane = tid & 31;
    const int wid  = tid >> 5;
    const int t    = blockIdx.x;
    const int b    = t >> 7;
    const int h    = t & 127;

    const uint32_t sbase = smem_u32(sm);

    // ---- zero the constant halo columns once (cols 3 and 132 of every row, both buffers) ----
    if (tid < 192) {
        int buf = tid >> 7;             // 0..1 for tid<192? need 2*16*3*2=192: decode below
        int rem = tid & 127;            // no: use full decode
        buf = tid / 96;
        rem = tid - buf*96;
        int cl  = rem / 6;
        int r6  = rem - cl*6;
        int r4  = r6 >> 1;
        int col = (r6 & 1) ? 132 : 3;
        sm[buf*BUF_FL + cl*XSTR + r4*ROWP + col] = 0.f;
    }

    // ---- staging (aligned 16B cp.async; OOB rows zero-filled) ----
    const float* xB  = x  + (size_t)b*Cch*HW;
    const float* gcB = gc + (size_t)b*Cch*HW + (size_t)h*Wwi;
    auto stage_chunk = [&](int cg) {
        const uint32_t dst0 = sbase + (cg & 1)*BUF_FL*4;
        const float* xc = xB + (size_t)cg*16*HW;
        // x: 16ch x 3rows x 32 segs of 16B
        #pragma unroll
        for (int it = 0; it < 6; ++it) {
            int idx = tid + it*THREADS;          // < 1536
            int cl  = idx / 96;
            int rem = idx - cl*96;
            int r4  = rem >> 5;
            int seg = rem & 31;
            int gh  = h - 1 + r4;
            bool inb = ((unsigned)gh < Hh);
            const float* src = inb ? (xc + (size_t)cl*HW + gh*Wwi + seg*4) : xB;
            cp16(dst0 + (uint32_t)(cl*XSTR + r4*ROWP + 4 + seg*4)*4, src, inb ? 16 : 0);
        }
        // gc: 16ch x 32 segs
        const float* gcc = gcB + (size_t)cg*16*HW;
        #pragma unroll
        for (int it = 0; it < 2; ++it) {
            int idx = tid + it*THREADS;          // < 512
            int cl  = idx >> 5;
            int seg = idx & 31;
            cp16(dst0 + (uint32_t)(XGC_OFF + cl*GCSTR + seg*4)*4,
                 gcc + (size_t)cl*HW + seg*4, 16);
        }
    };
    stage_chunk(0);
    cp_commit();

    const int r0 = wid*16 + (lane >> 2);
    const int r1 = r0 + 8;
    const int qp = (lane & 3)*2;

    // gs broadcast half2 for all 9 phases x 2 rows, packed once per tile
    const float* gsb = gsp + (size_t)b*9*HW + (size_t)h*Wwi;
    uint32_t gs2a[9], gs2b[9];
    #pragma unroll
    for (int p = 0; p < 9; ++p) {
        float v0 = __ldg(gsb + (size_t)p*HW + r0);
        float v1 = __ldg(gsb + (size_t)p*HW + r1);
        gs2a[p] = packh2(v0, v0);
        gs2b[p] = packh2(v1, v1);
    }

    float acc[32];
    #pragma unroll
    for (int i = 0; i < 32; ++i) acc[i] = 0.f;

    for (int g = 0; g < NSUPER; ++g) {
        if (g + 1 < NSUPER) { stage_chunk(g + 1); cp_commit(); cp_wait1(); }
        else                { cp_wait0(); }
        __syncthreads();

        const float* bs = sm + (g & 1)*BUF_FL;
        // per-thread channel base pointers (channels qp, qp+1, qp+8, qp+9)
        const float* p00 = bs + (qp    )*XSTR + r0;
        const float* p01 = bs + (qp    )*XSTR + r1;
        const float* p10 = bs + (qp + 1)*XSTR + r0;
        const float* p11 = bs + (qp + 1)*XSTR + r1;
        const float* p20 = bs + (qp + 8)*XSTR + r0;
        const float* p21 = bs + (qp + 8)*XSTR + r1;
        const float* p30 = bs + (qp + 9)*XSTR + r0;
        const float* p31 = bs + (qp + 9)*XSTR + r1;

        // gc channel-pairs packed to half2, hoisted per super-group
        const float* gp = bs + XGC_OFF;
        const uint32_t gc2_0 = packh2(gp[(qp    )*GCSTR + r0], gp[(qp + 1)*GCSTR + r0]);
        const uint32_t gc2_1 = packh2(gp[(qp    )*GCSTR + r1], gp[(qp + 1)*GCSTR + r1]);
        const uint32_t gc2_2 = packh2(gp[(qp + 8)*GCSTR + r0], gp[(qp + 9)*GCSTR + r0]);
        const uint32_t gc2_3 = packh2(gp[(qp + 8)*GCSTR + r1], gp[(qp + 9)*GCSTR + r1]);

        #pragma unroll
        for (int p = 0; p < NPH; ++p) {
            const int di  = p / 3;
            const int dj  = p - 3*di;
            const int imm = di*ROWP + dj + 3;     // gw = w + dj - 1 at col gw+4

            const uint4* bp = d_bfrag + (size_t)(g*NPH + p)*128 + lane;
            uint4 B0 = bp[0];
            uint4 B1 = bp[32];

            // x channel-pairs packed to half2
            const uint32_t xp0 = packh2(p00[imm], p10[imm]);
            const uint32_t xp1 = packh2(p01[imm], p11[imm]);
            const uint32_t xp2 = packh2(p20[imm], p30[imm]);
            const uint32_t xp3 = packh2(p21[imm], p31[imm]);

            // t = tanh(gc + gs) in f16x2; A = x + x*t
            const uint32_t t0 = tanh_h2(hadd2(gc2_0, gs2a[p]));
            const uint32_t t1 = tanh_h2(hadd2(gc2_1, gs2b[p]));
            const uint32_t t2 = tanh_h2(hadd2(gc2_2, gs2a[p]));
            const uint32_t t3 = tanh_h2(hadd2(gc2_3, gs2b[p]));

            const uint32_t a0 = hfma2(xp0, t0, xp0);
            const uint32_t a1 = hfma2(xp1, t1, xp1);
            const uint32_t a2 = hfma2(xp2, t2, xp2);
            const uint32_t a3 = hfma2(xp3, t3, xp3);

            hmma(acc[0],  acc[1],  acc[2],  acc[3],  a0,a1,a2,a3, B0.x, B0.y);
            hmma(acc[4],  acc[5],  acc[6],  acc[7],  a0,a1,a2,a3, B0.z, B0.w);
            hmma(acc[8],  acc[9],  acc[10], acc[11], a0,a1,a2,a3, B1.x, B1.y);
            hmma(acc[12], acc[13], acc[14], acc[15], a0,a1,a2,a3, B1.z, B1.w);

            uint4 B2 = bp[64];
            uint4 B3 = bp[96];
            hmma(acc[16], acc[17], acc[18], acc[19], a0,a1,a2,a3, B2.x, B2.y);
            hmma(acc[20], acc[21], acc[22], acc[23], a0,a1,a2,a3, B2.z, B2.w);
            hmma(acc[24], acc[25], acc[26], acc[27], a0,a1,a2,a3, B3.x, B3.y);
            hmma(acc[28], acc[29], acc[30], acc[31], a0,a1,a2,a3, B3.z, B3.w);
        }
        __syncthreads();   // all done reading bs before restaging
    }

    // ---- epilogue: D fragments -> out[b][o][h][w] ----
    float* ob = out + ((size_t)b*Och)*HW + (size_t)h*Wwi;
    #pragma unroll
    for (int nt = 0; nt < 8; ++nt) {
        const int o0 = nt*8 + qp;
        float* p = ob + (size_t)o0*HW;
        p[r0]      = acc[nt*4 + 0];
        p[HW + r0] = acc[nt*4 + 1];
        p[r1]      = acc[nt*4 + 2];
        p[HW + r1] = acc[nt*4 + 3];
    }
}

extern "C" void kernel_launch(void* const* d_in, const int* in_sizes, int n_in,
                              void* d_out, int out_size) {
    const float* x  = (const float*)d_in[0];
    const float* gc = (const float*)d_in[1];
    const float* gs = (const float*)d_in[2];
    const float* w  = (const float*)d_in[3];
    float* out = (float*)d_out;

    prep_bfrag<<<(NSTEPS*4*32 + 255)/256, 256>>>(w);

    const int smem_bytes = SMEM_FL * 4;
    (void)cudaFuncSetAttribute(paka_hmma,
                               cudaFuncAttributeMaxDynamicSharedMemorySize,
                               smem_bytes);
    paka_hmma<<<NTILES, THREADS, smem_bytes>>>(x, gc, gs, out);
}